// round 3
// baseline (speedup 1.0000x reference)
#include <cuda_runtime.h>
#include <cstdint>
#include <cstddef>

// Problem constants
#define BB 2
#define PP 4000
#define NPTS 4096
#define DD 64
#define DSC 64
#define MM 512
#define KK 8
#define NXX 432
#define NYY 496
#define HW (NXX*NYY)        // 214272

#define NSPLIT_PTS 8
#define PTS_PER_SPLIT (NPTS/NSPLIT_PTS)   // 512
#define NSPLIT_MEM 2
#define MEM_PER_SPLIT (MM/NSPLIT_MEM)     // 256
#define TILE_J 64
#define SLOT_STRIDE (NSPLIT_PTS*KK)       // 64 candidate slots per pillar

// ---- device scratch (no allocations allowed) ----
__device__ int   g_winner[BB*HW];                 // last-wins owner per grid cell
__device__ float g_topv[(size_t)BB*PP*SLOT_STRIDE];
__device__ int   g_topi[(size_t)BB*PP*SLOT_STRIDE];

// ---- packed fp32x2 helpers (Blackwell paired-FP32 pipe) ----
typedef unsigned long long u64t;
__device__ __forceinline__ u64t pk2(float x, float y) {
    u64t r; asm("mov.b64 %0, {%1, %2};" : "=l"(r) : "f"(x), "f"(y)); return r;
}
__device__ __forceinline__ void up2(u64t a, float& x, float& y) {
    asm("mov.b64 {%0, %1}, %2;" : "=f"(x), "=f"(y) : "l"(a));
}
__device__ __forceinline__ void fma2(u64t& d, u64t a, u64t b) {
    asm("fma.rn.f32x2 %0, %1, %2, %0;" : "+l"(d) : "l"(a), "l"(b));
}

// ---- register-resident top-8 insertion (strict > keeps earliest index on ties,
//      matching jax.lax.top_k lower-index tie-break) ----
__device__ __forceinline__ void ins8(float v, int id, float tv[KK], int ti[KK],
                                     float& vmin, int& pmin) {
    if (v > vmin) {
#pragma unroll
        for (int k = 0; k < KK; k++) if (k == pmin) { tv[k] = v; ti[k] = id; }
        vmin = tv[0]; pmin = 0;
#pragma unroll
        for (int k = 1; k < KK; k++) if (tv[k] < vmin) { vmin = tv[k]; pmin = k; }
    }
}

// ============================================================================
// Kernel 1: fused (pillars x rows^T) partial matmul + per-pillar top-8.
// rows = point_features (per batch) or memory_weight (shared, stride 0).
// grid: (ceil(P/128), nsplit, B), block 128. Each thread owns one pillar,
// pillar vector lives in 64 registers (32 packed f32x2 pairs).
// ============================================================================
__global__ void __launch_bounds__(128)
k_partial_topk(const float* __restrict__ pillars,
               const float* __restrict__ rows, int rowBatchStride,
               int perSplit)
{
    const int b     = blockIdx.z;
    const int split = blockIdx.y;
    const int p     = blockIdx.x * 128 + threadIdx.x;
    const bool active = (p < PP);
    const float* rsrc = rows + (size_t)b * rowBatchStride;
    const int base = split * perSplit;

    __shared__ __align__(16) float spt[TILE_J * DD];

    u64t pr[32];
    if (active) {
        const float4* prow = (const float4*)(pillars + ((size_t)b * PP + p) * DD);
#pragma unroll
        for (int q = 0; q < 16; q++) {
            float4 v = prow[q];
            pr[2*q]   = pk2(v.x, v.y);
            pr[2*q+1] = pk2(v.z, v.w);
        }
    }

    float tv[KK]; int ti[KK];
#pragma unroll
    for (int k = 0; k < KK; k++) { tv[k] = -3.0e38f; ti[k] = 0; }
    float vmin = -3.0e38f; int pmin = 0;

    const int ntiles = perSplit / TILE_J;
    for (int t = 0; t < ntiles; t++) {
        const int tb = base + t * TILE_J;
        // cooperative coalesced tile load: 64 rows x 64 floats = 1024 float4
        const float4* gsrc = (const float4*)(rsrc + (size_t)tb * DD);
#pragma unroll
        for (int r = 0; r < 8; r++)
            ((float4*)spt)[r * 128 + threadIdx.x] = gsrc[r * 128 + threadIdx.x];
        __syncthreads();

        if (active) {
            for (int j = 0; j < TILE_J; j += 4) {
                // 4 rows at once, even/odd split accumulators -> 8 independent
                // FMA chains (hides lat=4 at rt=2)
                u64t a0e=0,a0o=0,a1e=0,a1o=0,a2e=0,a2o=0,a3e=0,a3o=0;
                const ulonglong2* r0 = (const ulonglong2*)&spt[(j+0)*DD];
                const ulonglong2* r1 = (const ulonglong2*)&spt[(j+1)*DD];
                const ulonglong2* r2 = (const ulonglong2*)&spt[(j+2)*DD];
                const ulonglong2* r3 = (const ulonglong2*)&spt[(j+3)*DD];
#pragma unroll
                for (int q = 0; q < 16; q++) {
                    ulonglong2 x0 = r0[q], x1 = r1[q], x2 = r2[q], x3 = r3[q];
                    fma2(a0e, pr[2*q], x0.x); fma2(a0o, pr[2*q+1], x0.y);
                    fma2(a1e, pr[2*q], x1.x); fma2(a1o, pr[2*q+1], x1.y);
                    fma2(a2e, pr[2*q], x2.x); fma2(a2o, pr[2*q+1], x2.y);
                    fma2(a3e, pr[2*q], x3.x); fma2(a3o, pr[2*q+1], x3.y);
                }
                float xa, xb, ya, yb, v;
                up2(a0e, xa, xb); up2(a0o, ya, yb); v = (xa + ya) + (xb + yb);
                ins8(v, tb + j + 0, tv, ti, vmin, pmin);
                up2(a1e, xa, xb); up2(a1o, ya, yb); v = (xa + ya) + (xb + yb);
                ins8(v, tb + j + 1, tv, ti, vmin, pmin);
                up2(a2e, xa, xb); up2(a2o, ya, yb); v = (xa + ya) + (xb + yb);
                ins8(v, tb + j + 2, tv, ti, vmin, pmin);
                up2(a3e, xa, xb); up2(a3o, ya, yb); v = (xa + ya) + (xb + yb);
                ins8(v, tb + j + 3, tv, ti, vmin, pmin);
            }
        }
        __syncthreads();
    }

    if (active) {
        const size_t o = ((size_t)b * PP + p) * SLOT_STRIDE + (size_t)split * KK;
#pragma unroll
        for (int k = 0; k < KK; k++) { g_topv[o + k] = tv[k]; g_topi[o + k] = ti[k]; }
    }
}

// ============================================================================
// Kernel 2: merge per-split candidates -> final top-8, fp32 softmax over the
// 8 exact logits, gather the 8 source rows, weighted sum -> dst[g*64 .. +64).
// ============================================================================
__global__ void __launch_bounds__(128)
k_merge(int nsplit, const float* __restrict__ rows, int rowBatchStride,
        float* __restrict__ dst)
{
    const int g = blockIdx.x * 128 + threadIdx.x;
    if (g >= BB * PP) return;
    const int b = g / PP;
    const float* rsrc = rows + (size_t)b * rowBatchStride;
    const size_t o = (size_t)g * SLOT_STRIDE;

    float tv[KK]; int ti[KK];
#pragma unroll
    for (int k = 0; k < KK; k++) { tv[k] = -3.0e38f; ti[k] = 0; }
    float vmin = -3.0e38f; int pmin = 0;

    const int n = nsplit * KK;
    for (int s = 0; s < n; s++)
        ins8(g_topv[o + s], g_topi[o + s], tv, ti, vmin, pmin);

    // softmax over the exact fp32 top-8 logits
    float m = tv[0];
#pragma unroll
    for (int k = 1; k < KK; k++) m = fmaxf(m, tv[k]);
    float w[KK]; float ssum = 0.0f;
#pragma unroll
    for (int k = 0; k < KK; k++) { w[k] = expf(tv[k] - m); ssum += w[k]; }
    const float inv = 1.0f / ssum;

    float4 acc[16];
#pragma unroll
    for (int q = 0; q < 16; q++) acc[q] = make_float4(0.f, 0.f, 0.f, 0.f);
#pragma unroll
    for (int k = 0; k < KK; k++) {
        const float wk = w[k] * inv;
        const float4* row = (const float4*)(rsrc + (size_t)ti[k] * DD);
#pragma unroll
        for (int q = 0; q < 16; q++) {
            float4 r = row[q];
            acc[q].x += wk * r.x; acc[q].y += wk * r.y;
            acc[q].z += wk * r.z; acc[q].w += wk * r.w;
        }
    }
    float4* out = (float4*)(dst + (size_t)g * DD);
#pragma unroll
    for (int q = 0; q < 16; q++) out[q] = acc[q];
}

// ============================================================================
// Winner pass (last-wins scatter semantics: max pillar index per cell)
// ============================================================================
__global__ void k_winner_init() {
    int i = blockIdx.x * 256 + threadIdx.x;
    if (i < BB * HW) g_winner[i] = -1;
}

__global__ void k_winner_mark(const int* __restrict__ idx) {
    int g = blockIdx.x * 256 + threadIdx.x;
    if (g >= BB * PP) return;
    int b = g / PP;
    int hw = idx[g];
    atomicMax(&g_winner[b * HW + hw], g - b * PP);
}

// ============================================================================
// Scatter: one warp per pillar; only winners write their 320 channel values.
// Grid planes already zeroed by cudaMemsetAsync.
//   out1[b][c][hw]: c<64 = pillars, c>=64 = pos_mem     (spatial_features)
//   out2[b][c][hw]: c<64 = pillars, c>=64 = pos_point   (spatial_features_point)
//   out3[b][c][hw]: pillar_scale                         (spatial_scale_features)
// ============================================================================
__global__ void __launch_bounds__(128)
k_scatter(const float* __restrict__ pillars, const float* __restrict__ scale,
          const int* __restrict__ idx,
          const float* __restrict__ pos_point, const float* __restrict__ pos_mem,
          float* __restrict__ out)
{
    const int gp = blockIdx.x * 4 + (threadIdx.x >> 5);
    if (gp >= BB * PP) return;
    const int lane = threadIdx.x & 31;
    const int b = gp / PP, p = gp - b * PP;
    const int hw = idx[gp];
    if (g_winner[b * HW + hw] != p) return;

    const float* pil = pillars   + (size_t)gp * DD;
    const float* sc  = scale     + (size_t)gp * DSC;
    const float* pm  = pos_mem   + (size_t)gp * DD;
    const float* ppt = pos_point + (size_t)gp * DD;

    float* out1 = out;
    float* out2 = out + (size_t)BB * 128 * HW;
    float* out3 = out + (size_t)2 * BB * 128 * HW;

    for (int c = lane; c < 64; c += 32) {
        const float pv = pil[c];
        out1[((size_t)b * 128 + c)      * HW + hw] = pv;
        out1[((size_t)b * 128 + 64 + c) * HW + hw] = pm[c];
        out2[((size_t)b * 128 + c)      * HW + hw] = pv;
        out2[((size_t)b * 128 + 64 + c) * HW + hw] = ppt[c];
        out3[((size_t)b * 64 + c)       * HW + hw] = sc[c];
    }
}

// ============================================================================
// kernel_launch — graph-capturable, allocation-free, default stream only.
// Input order (metadata): pillar_features, pillar_scale_features,
//                         point_features, memory_weight, indices
// Output order: sp, sp_point, sp_scale, pos_point, pos_mem (fp32, concatenated)
// ============================================================================
extern "C" void kernel_launch(void* const* d_in, const int* in_sizes, int n_in,
                              void* d_out, int out_size)
{
    const float* pillars = (const float*)d_in[0];
    const float* scale   = (const float*)d_in[1];
    const float* points  = (const float*)d_in[2];
    const float* W       = (const float*)d_in[3];
    const int*   idx     = (const int*)  d_in[4];
    float* out = (float*)d_out;

    const size_t sz12   = (size_t)BB * 128 * HW;   // per dense 128-ch grid
    const size_t sz3    = (size_t)BB * 64 * HW;    // scale grid
    const size_t grids  = 2 * sz12 + sz3;          // 137,134,080 floats
    float* out4 = out + grids;                     // point_positive [B*P, 64]
    float* out5 = out4 + (size_t)BB * PP * DD;     // memory_positive [B*P, 64]

    // zero the dense grids (capturable async memset)
    cudaMemsetAsync(d_out, 0, grids * sizeof(float));

    k_winner_init<<<(BB * HW + 255) / 256, 256>>>();

    // point attention: (pillars x points^T) top-8 -> softmax -> pos_point
    k_partial_topk<<<dim3((PP + 127) / 128, NSPLIT_PTS, BB), 128>>>(
        pillars, points, NPTS * DD, PTS_PER_SPLIT);
    k_merge<<<(BB * PP + 127) / 128, 128>>>(NSPLIT_PTS, points, NPTS * DD, out4);

    // memory attention: (pillars x W^T) top-8 -> softmax -> pos_mem
    // (reuses the same scratch; stream ordering guarantees the merge above
    //  consumed it first)
    k_partial_topk<<<dim3((PP + 127) / 128, NSPLIT_MEM, BB), 128>>>(
        pillars, W, 0, MEM_PER_SPLIT);
    k_merge<<<(BB * PP + 127) / 128, 128>>>(NSPLIT_MEM, W, 0, out5);

    // last-wins winner resolution, then sparse scatter into the zeroed grids
    k_winner_mark<<<(BB * PP + 255) / 256, 256>>>(idx);
    k_scatter<<<(BB * PP + 3) / 4, 128>>>(pillars, scale, idx, out4, out5, out);
}

// round 5
// speedup vs baseline: 1.9051x; 1.9051x over previous
#include <cuda_runtime.h>
#include <cstdint>
#include <cstddef>

// Problem constants
#define BB 2
#define PP 4000
#define NPTS 4096
#define DD 64
#define DSC 64
#define MM 512
#define KK 8
#define NXX 432
#define NYY 496
#define HW (NXX*NYY)        // 214272

#define NSPLIT_PTS 16
#define PTS_PER_SPLIT (NPTS/NSPLIT_PTS)   // 256
#define NSPLIT_MEM 8
#define MEM_PER_SPLIT (MM/NSPLIT_MEM)     // 64
#define TILE_J 64
#define PTS_SLOTS (NSPLIT_PTS*KK)         // 128
#define MEM_SLOTS (NSPLIT_MEM*KK)         // 64
#define TOT_SLOTS (PTS_SLOTS+MEM_SLOTS)   // 192
#define BPP (BB*PP)                       // 8000
#define PLANES 320
#define PLANES_PER_BLK 32

// ---- device scratch (no allocations allowed; 16B-aligned for LDG.128) ----
__device__ __align__(16) int   g_winner[BB*HW];
__device__ __align__(16) float g_topv[(size_t)TOT_SLOTS*BPP];   // [slot][b*P+p]
__device__ __align__(16) int   g_topi[(size_t)TOT_SLOTS*BPP];

// ---- packed fp32x2 helpers (Blackwell paired-FP32 pipe) ----
typedef unsigned long long u64t;
__device__ __forceinline__ u64t pk2(float x, float y) {
    u64t r; asm("mov.b64 %0, {%1, %2};" : "=l"(r) : "f"(x), "f"(y)); return r;
}
__device__ __forceinline__ void up2(u64t a, float& x, float& y) {
    asm("mov.b64 {%0, %1}, %2;" : "=f"(x), "=f"(y) : "l"(a));
}
__device__ __forceinline__ void fma2(u64t& d, u64t a, u64t b) {
    asm("fma.rn.f32x2 %0, %1, %2, %0;" : "+l"(d) : "l"(a), "l"(b));
}

// ---- register-resident top-8 insertion (strict > keeps earliest index on
//      ties, matching jax.lax.top_k tie-break) ----
__device__ __forceinline__ void ins8(float v, int id, float tv[KK], int ti[KK],
                                     float& vmin, int& pmin) {
    if (v > vmin) {
#pragma unroll
        for (int k = 0; k < KK; k++) if (k == pmin) { tv[k] = v; ti[k] = id; }
        vmin = tv[0]; pmin = 0;
#pragma unroll
        for (int k = 1; k < KK; k++) if (tv[k] < vmin) { vmin = tv[k]; pmin = k; }
    }
}

// ============================================================================
// Combined top-k kernel: both attention matmuls in ONE launch.
//   blockIdx.y <  NSPLIT_PTS          : points split (256 rows/thread)
//   blockIdx.y >= NSPLIT_PTS (8 more) : memory-weight split (64 rows/thread)
// One thread = one pillar; pillar vector in 32 packed f32x2 registers.
// ============================================================================
__global__ void __launch_bounds__(128)
k_topk_all(const float* __restrict__ pillars,
           const float* __restrict__ points,
           const float* __restrict__ W)
{
    const int b = blockIdx.z;
    const int y = blockIdx.y;
    const int p = blockIdx.x * 128 + threadIdx.x;
    const bool active = (p < PP);

    const float* rsrc;
    int base, perSplit, slotBase;
    if (y < NSPLIT_PTS) {
        rsrc = points + (size_t)b * NPTS * DD;
        base = y * PTS_PER_SPLIT; perSplit = PTS_PER_SPLIT; slotBase = y * KK;
    } else {
        rsrc = W;
        base = (y - NSPLIT_PTS) * MEM_PER_SPLIT; perSplit = MEM_PER_SPLIT;
        slotBase = PTS_SLOTS + (y - NSPLIT_PTS) * KK;
    }

    __shared__ __align__(16) float spt[TILE_J * DD];

    u64t pr[32];
    if (active) {
        const float4* prow = (const float4*)(pillars + ((size_t)b * PP + p) * DD);
#pragma unroll
        for (int q = 0; q < 16; q++) {
            float4 v = prow[q];
            pr[2*q]   = pk2(v.x, v.y);
            pr[2*q+1] = pk2(v.z, v.w);
        }
    }

    float tv[KK]; int ti[KK];
#pragma unroll
    for (int k = 0; k < KK; k++) { tv[k] = -3.0e38f; ti[k] = 0; }
    float vmin = -3.0e38f; int pmin = 0;

    const int ntiles = perSplit / TILE_J;
    for (int t = 0; t < ntiles; t++) {
        const int tb = base + t * TILE_J;
        const float4* gsrc = (const float4*)(rsrc + (size_t)tb * DD);
#pragma unroll
        for (int r = 0; r < 8; r++)
            ((float4*)spt)[r * 128 + threadIdx.x] = gsrc[r * 128 + threadIdx.x];
        __syncthreads();

        if (active) {
            for (int j = 0; j < TILE_J; j += 4) {
                // 4 rows at once, even/odd split accumulators -> 8 independent
                // FMA chains (hides lat=4 at rt=2)
                u64t a0e=0,a0o=0,a1e=0,a1o=0,a2e=0,a2o=0,a3e=0,a3o=0;
                const ulonglong2* r0 = (const ulonglong2*)&spt[(j+0)*DD];
                const ulonglong2* r1 = (const ulonglong2*)&spt[(j+1)*DD];
                const ulonglong2* r2 = (const ulonglong2*)&spt[(j+2)*DD];
                const ulonglong2* r3 = (const ulonglong2*)&spt[(j+3)*DD];
#pragma unroll
                for (int q = 0; q < 16; q++) {
                    ulonglong2 x0 = r0[q], x1 = r1[q], x2 = r2[q], x3 = r3[q];
                    fma2(a0e, pr[2*q], x0.x); fma2(a0o, pr[2*q+1], x0.y);
                    fma2(a1e, pr[2*q], x1.x); fma2(a1o, pr[2*q+1], x1.y);
                    fma2(a2e, pr[2*q], x2.x); fma2(a2o, pr[2*q+1], x2.y);
                    fma2(a3e, pr[2*q], x3.x); fma2(a3o, pr[2*q+1], x3.y);
                }
                float xa, xb, ya, yb, v;
                up2(a0e, xa, xb); up2(a0o, ya, yb); v = (xa + ya) + (xb + yb);
                ins8(v, tb + j + 0, tv, ti, vmin, pmin);
                up2(a1e, xa, xb); up2(a1o, ya, yb); v = (xa + ya) + (xb + yb);
                ins8(v, tb + j + 1, tv, ti, vmin, pmin);
                up2(a2e, xa, xb); up2(a2o, ya, yb); v = (xa + ya) + (xb + yb);
                ins8(v, tb + j + 2, tv, ti, vmin, pmin);
                up2(a3e, xa, xb); up2(a3o, ya, yb); v = (xa + ya) + (xb + yb);
                ins8(v, tb + j + 3, tv, ti, vmin, pmin);
            }
        }
        __syncthreads();
    }

    if (active) {
        const int g = b * PP + p;
#pragma unroll
        for (int k = 0; k < KK; k++) {
            g_topv[(size_t)(slotBase + k) * BPP + g] = tv[k];
            g_topi[(size_t)(slotBase + k) * BPP + g] = ti[k];
        }
    }
}

// ============================================================================
// Combined merge: final top-8 + fp32 softmax + gather + weighted sum.
//   blockIdx.y == 0 : points attention -> pos_point
//   blockIdx.y == 1 : memory attention -> pos_mem
// ============================================================================
__global__ void __launch_bounds__(128)
k_merge_all(const float* __restrict__ points, const float* __restrict__ W,
            float* __restrict__ out4, float* __restrict__ out5)
{
    const int g = blockIdx.x * 128 + threadIdx.x;
    if (g >= BPP) return;
    const int b = g / PP;
    const bool isMem = (blockIdx.y == 1);
    const float* rsrc = isMem ? W : points + (size_t)b * NPTS * DD;
    const int slotBase = isMem ? PTS_SLOTS : 0;
    const int nslots   = isMem ? MEM_SLOTS : PTS_SLOTS;
    float* dst = (isMem ? out5 : out4) + (size_t)g * DD;

    float tv[KK]; int ti[KK];
#pragma unroll
    for (int k = 0; k < KK; k++) { tv[k] = -3.0e38f; ti[k] = 0; }
    float vmin = -3.0e38f; int pmin = 0;

    for (int s = 0; s < nslots; s++) {
        const size_t o = (size_t)(slotBase + s) * BPP + g;
        ins8(g_topv[o], g_topi[o], tv, ti, vmin, pmin);
    }

    float m = tv[0];
#pragma unroll
    for (int k = 1; k < KK; k++) m = fmaxf(m, tv[k]);
    float w[KK]; float ssum = 0.0f;
#pragma unroll
    for (int k = 0; k < KK; k++) { w[k] = expf(tv[k] - m); ssum += w[k]; }
    const float inv = 1.0f / ssum;

    float4 acc[16];
#pragma unroll
    for (int q = 0; q < 16; q++) acc[q] = make_float4(0.f, 0.f, 0.f, 0.f);
#pragma unroll
    for (int k = 0; k < KK; k++) {
        const float wk = w[k] * inv;
        const float4* row = (const float4*)(rsrc + (size_t)ti[k] * DD);
#pragma unroll
        for (int q = 0; q < 16; q++) {
            float4 r = row[q];
            acc[q].x += wk * r.x; acc[q].y += wk * r.y;
            acc[q].z += wk * r.z; acc[q].w += wk * r.w;
        }
    }
    float4* out = (float4*)dst;
#pragma unroll
    for (int q = 0; q < 16; q++) out[q] = acc[q];
}

// ============================================================================
// Winner pass (last-wins scatter semantics: max pillar index per cell)
// ============================================================================
__global__ void k_winner_init() {
    int i = blockIdx.x * 256 + threadIdx.x;
    if (i < BB * HW) g_winner[i] = -1;
}

__global__ void k_winner_mark(const int* __restrict__ idx) {
    int g = blockIdx.x * 256 + threadIdx.x;
    if (g >= BPP) return;
    int b = g / PP;
    atomicMax(&g_winner[b * HW + idx[g]], g - b * PP);
}

// ============================================================================
// Dense gather-fill: replaces memset + scatter. Each thread owns 4 consecutive
// grid cells (winner int4 kept in registers), loops over 32 channel-planes
// writing coalesced float4 stores (zero or gathered winner value).
// Planes t: [0,64) grid1/pillars, [64,128) grid1/pos_mem,
//           [128,192) grid2/pillars, [192,256) grid2/pos_point,
//           [256,320) grid3/scale.
// ============================================================================
__global__ void __launch_bounds__(256)
k_fill(const float* __restrict__ pillars, const float* __restrict__ scale,
       const float* __restrict__ pos_point, const float* __restrict__ pos_mem,
       float* __restrict__ out)
{
    const int b = blockIdx.z;
    const int hw = (blockIdx.x * 256 + threadIdx.x) * 4;
    if (hw >= HW) return;

    const int4 w = *(const int4*)&g_winner[b * HW + hw];
    const int wm = max(max(w.x, w.y), max(w.z, w.w));
    const bool any = (wm >= 0);
    const size_t G1 = (size_t)BB * 128 * HW;

    const int t0 = blockIdx.y * PLANES_PER_BLK;
#pragma unroll 4
    for (int t = t0; t < t0 + PLANES_PER_BLK; t++) {
        const float* A; int cc; size_t ob;
        if (t < 64)       { A = pillars;   cc = t;       ob = ((size_t)b*128 + t) * HW; }
        else if (t < 128) { A = pos_mem;   cc = t - 64;  ob = ((size_t)b*128 + t) * HW; }
        else if (t < 192) { A = pillars;   cc = t - 128; ob = G1 + ((size_t)b*128 + (t-128)) * HW; }
        else if (t < 256) { A = pos_point; cc = t - 192; ob = G1 + ((size_t)b*128 + (t-128)) * HW; }
        else              { A = scale;     cc = t - 256; ob = 2*G1 + ((size_t)b*64 + (t-256)) * HW; }

        float4 v = make_float4(0.f, 0.f, 0.f, 0.f);
        if (any) {
            const float* Ab = A + (size_t)b * PP * 64 + cc;
            if (w.x >= 0) v.x = Ab[(size_t)w.x * 64];
            if (w.y >= 0) v.y = Ab[(size_t)w.y * 64];
            if (w.z >= 0) v.z = Ab[(size_t)w.z * 64];
            if (w.w >= 0) v.w = Ab[(size_t)w.w * 64];
        }
        *(float4*)(out + ob + hw) = v;
    }
}

// ============================================================================
// kernel_launch — graph-capturable, allocation-free.
// Inputs: pillar_features, pillar_scale_features, point_features,
//         memory_weight, indices
// Output: sp, sp_point, sp_scale, pos_point, pos_mem (fp32, concatenated)
// ============================================================================
extern "C" void kernel_launch(void* const* d_in, const int* in_sizes, int n_in,
                              void* d_out, int out_size)
{
    const float* pillars = (const float*)d_in[0];
    const float* scale   = (const float*)d_in[1];
    const float* points  = (const float*)d_in[2];
    const float* W       = (const float*)d_in[3];
    const int*   idx     = (const int*)  d_in[4];
    float* out = (float*)d_out;

    const size_t sz12  = (size_t)BB * 128 * HW;
    const size_t sz3   = (size_t)BB * 64 * HW;
    const size_t grids = 2 * sz12 + sz3;
    float* out4 = out + grids;                   // point_positive [B*P, 64]
    float* out5 = out4 + (size_t)BPP * DD;       // memory_positive [B*P, 64]

    // winner resolution first (only depends on idx)
    k_winner_init<<<(BB * HW + 255) / 256, 256>>>();
    k_winner_mark<<<(BPP + 255) / 256, 256>>>(idx);

    // both attention matmuls + top-8 in one launch (1536 blocks)
    k_topk_all<<<dim3((PP + 127) / 128, NSPLIT_PTS + NSPLIT_MEM, BB), 128>>>(
        pillars, points, W);

    // both merges in one launch
    k_merge_all<<<dim3((BPP + 127) / 128, 2), 128>>>(points, W, out4, out5);

    // dense gather-fill of all three grids (no memset needed)
    k_fill<<<dim3((HW / 4 + 255) / 256, PLANES / PLANES_PER_BLK, BB), 256>>>(
        pillars, scale, out4, out5, out);
}

// round 6
// speedup vs baseline: 2.2607x; 1.1867x over previous
#include <cuda_runtime.h>
#include <cstdint>
#include <cstddef>

// Problem constants
#define BB 2
#define PP 4000
#define NPTS 4096
#define DD 64
#define DSC 64
#define MM 512
#define KK 8
#define NXX 432
#define NYY 496
#define HW (NXX*NYY)        // 214272

#define NSPLIT_PTS 16
#define PTS_PER_SPLIT (NPTS/NSPLIT_PTS)   // 256
#define NSPLIT_MEM 8
#define MEM_PER_SPLIT (MM/NSPLIT_MEM)     // 64
#define TILE_J 64
#define PTS_SLOTS (NSPLIT_PTS*KK)         // 128
#define MEM_SLOTS (NSPLIT_MEM*KK)         // 64
#define SLOT_STRIDE (PTS_SLOTS+MEM_SLOTS) // 192 per pillar: [0,128) pts, [128,192) mem
#define BPP (BB*PP)                       // 8000
#define PLANES 320
#define PLANES_PER_BLK 32

// ---- device scratch (no allocations allowed; 16B-aligned) ----
__device__ __align__(16) int   g_winner[BB*HW];
__device__ __align__(16) float g_topv[(size_t)BPP*SLOT_STRIDE];   // [g][slot]
__device__ __align__(16) int   g_topi[(size_t)BPP*SLOT_STRIDE];

// ---- packed fp32x2 helpers (Blackwell paired-FP32 pipe) ----
typedef unsigned long long u64t;
__device__ __forceinline__ u64t pk2(float x, float y) {
    u64t r; asm("mov.b64 %0, {%1, %2};" : "=l"(r) : "f"(x), "f"(y)); return r;
}
__device__ __forceinline__ void up2(u64t a, float& x, float& y) {
    asm("mov.b64 {%0, %1}, %2;" : "=f"(x), "=f"(y) : "l"(a));
}
__device__ __forceinline__ void fma2(u64t& d, u64t a, u64t b) {
    asm("fma.rn.f32x2 %0, %1, %2, %0;" : "+l"(d) : "l"(a), "l"(b));
}

// ---- register-resident top-8 insertion ----
__device__ __forceinline__ void ins8(float v, int id, float tv[KK], int ti[KK],
                                     float& vmin, int& pmin) {
    if (v > vmin) {
#pragma unroll
        for (int k = 0; k < KK; k++) if (k == pmin) { tv[k] = v; ti[k] = id; }
        vmin = tv[0]; pmin = 0;
#pragma unroll
        for (int k = 1; k < KK; k++) if (tv[k] < vmin) { vmin = tv[k]; pmin = k; }
    }
}

// ============================================================================
// Combined top-k kernel: both attention matmuls in ONE launch.
//   blockIdx.y <  NSPLIT_PTS          : points split (256 rows/thread)
//   blockIdx.y >= NSPLIT_PTS (8 more) : memory-weight split (64 rows/thread)
// One thread = one pillar; pillar vector in 32 packed f32x2 registers.
// ============================================================================
__global__ void __launch_bounds__(128)
k_topk_all(const float* __restrict__ pillars,
           const float* __restrict__ points,
           const float* __restrict__ W)
{
    const int b = blockIdx.z;
    const int y = blockIdx.y;
    const int p = blockIdx.x * 128 + threadIdx.x;
    const bool active = (p < PP);

    const float* rsrc;
    int base, perSplit, slotBase;
    if (y < NSPLIT_PTS) {
        rsrc = points + (size_t)b * NPTS * DD;
        base = y * PTS_PER_SPLIT; perSplit = PTS_PER_SPLIT; slotBase = y * KK;
    } else {
        rsrc = W;
        base = (y - NSPLIT_PTS) * MEM_PER_SPLIT; perSplit = MEM_PER_SPLIT;
        slotBase = PTS_SLOTS + (y - NSPLIT_PTS) * KK;
    }

    __shared__ __align__(16) float spt[TILE_J * DD];

    u64t pr[32];
    if (active) {
        const float4* prow = (const float4*)(pillars + ((size_t)b * PP + p) * DD);
#pragma unroll
        for (int q = 0; q < 16; q++) {
            float4 v = prow[q];
            pr[2*q]   = pk2(v.x, v.y);
            pr[2*q+1] = pk2(v.z, v.w);
        }
    }

    float tv[KK]; int ti[KK];
#pragma unroll
    for (int k = 0; k < KK; k++) { tv[k] = -3.0e38f; ti[k] = 0; }
    float vmin = -3.0e38f; int pmin = 0;

    const int ntiles = perSplit / TILE_J;
    for (int t = 0; t < ntiles; t++) {
        const int tb = base + t * TILE_J;
        const float4* gsrc = (const float4*)(rsrc + (size_t)tb * DD);
#pragma unroll
        for (int r = 0; r < 8; r++)
            ((float4*)spt)[r * 128 + threadIdx.x] = gsrc[r * 128 + threadIdx.x];
        __syncthreads();

        if (active) {
            for (int j = 0; j < TILE_J; j += 4) {
                // 4 rows at once, even/odd split accumulators -> 8 independent
                // FMA chains (hides lat=4 at rt=2)
                u64t a0e=0,a0o=0,a1e=0,a1o=0,a2e=0,a2o=0,a3e=0,a3o=0;
                const ulonglong2* r0 = (const ulonglong2*)&spt[(j+0)*DD];
                const ulonglong2* r1 = (const ulonglong2*)&spt[(j+1)*DD];
                const ulonglong2* r2 = (const ulonglong2*)&spt[(j+2)*DD];
                const ulonglong2* r3 = (const ulonglong2*)&spt[(j+3)*DD];
#pragma unroll
                for (int q = 0; q < 16; q++) {
                    ulonglong2 x0 = r0[q], x1 = r1[q], x2 = r2[q], x3 = r3[q];
                    fma2(a0e, pr[2*q], x0.x); fma2(a0o, pr[2*q+1], x0.y);
                    fma2(a1e, pr[2*q], x1.x); fma2(a1o, pr[2*q+1], x1.y);
                    fma2(a2e, pr[2*q], x2.x); fma2(a2o, pr[2*q+1], x2.y);
                    fma2(a3e, pr[2*q], x3.x); fma2(a3o, pr[2*q+1], x3.y);
                }
                float xa, xb, ya, yb, v;
                up2(a0e, xa, xb); up2(a0o, ya, yb); v = (xa + ya) + (xb + yb);
                ins8(v, tb + j + 0, tv, ti, vmin, pmin);
                up2(a1e, xa, xb); up2(a1o, ya, yb); v = (xa + ya) + (xb + yb);
                ins8(v, tb + j + 1, tv, ti, vmin, pmin);
                up2(a2e, xa, xb); up2(a2o, ya, yb); v = (xa + ya) + (xb + yb);
                ins8(v, tb + j + 2, tv, ti, vmin, pmin);
                up2(a3e, xa, xb); up2(a3o, ya, yb); v = (xa + ya) + (xb + yb);
                ins8(v, tb + j + 3, tv, ti, vmin, pmin);
            }
        }
        __syncthreads();
    }

    if (active) {
        const size_t o = (size_t)(b * PP + p) * SLOT_STRIDE + slotBase;
#pragma unroll
        for (int k = 0; k < KK; k++) { g_topv[o + k] = tv[k]; g_topi[o + k] = ti[k]; }
    }
}

// ============================================================================
// Warp-per-task merge: 16000 warps (8000 pillars x {point, mem}).
// Lane-parallel candidate load -> 8 rounds of warp arg-max -> softmax ->
// cooperative gather (lane owns 2 channels) -> coalesced float2 store.
// ============================================================================
__global__ void __launch_bounds__(256)
k_merge_warp(const float* __restrict__ points, const float* __restrict__ W,
             float* __restrict__ out4, float* __restrict__ out5)
{
    const int wid  = blockIdx.x * 8 + (threadIdx.x >> 5);
    if (wid >= 2 * BPP) return;
    const int lane = threadIdx.x & 31;
    const int g    = wid >> 1;
    const bool isMem = (wid & 1);
    const int b = g / PP;

    const float* rsrc = isMem ? W : points + (size_t)b * NPTS * DD;
    const int base = isMem ? PTS_SLOTS : 0;
    const int nc   = isMem ? (MEM_SLOTS / 32) : (PTS_SLOTS / 32);   // 2 or 4
    float* dst = (isMem ? out5 : out4) + (size_t)g * DD;

    // lane-local candidates (coalesced loads; unused slots = -inf)
    const size_t o = (size_t)g * SLOT_STRIDE + base;
    float cv[4]; int ci[4];
#pragma unroll
    for (int j = 0; j < 4; j++) {
        if (j < nc) { cv[j] = g_topv[o + j*32 + lane]; ci[j] = g_topi[o + j*32 + lane]; }
        else        { cv[j] = -3.0e38f; ci[j] = 0x7FFFFFFF; }
    }

    // 8 rounds of warp arg-max (candidate row indices are globally unique)
    float tvk[KK]; int tik[KK];
#pragma unroll
    for (int k = 0; k < KK; k++) {
        float bv = cv[0]; int bi = ci[0];
#pragma unroll
        for (int j = 1; j < 4; j++)
            if (cv[j] > bv || (cv[j] == bv && ci[j] < bi)) { bv = cv[j]; bi = ci[j]; }
#pragma unroll
        for (int off = 16; off; off >>= 1) {
            float ov = __shfl_xor_sync(0xFFFFFFFFu, bv, off);
            int   oi = __shfl_xor_sync(0xFFFFFFFFu, bi, off);
            if (ov > bv || (ov == bv && oi < bi)) { bv = ov; bi = oi; }
        }
        tvk[k] = bv; tik[k] = bi;
        // consume (index match is unique chip-wide within this task)
#pragma unroll
        for (int j = 0; j < 4; j++)
            if (ci[j] == bi) cv[j] = -3.0e38f;
    }

    // softmax over exact fp32 top-8 logits (tvk[0] is the max by construction)
    const float m = tvk[0];
    float w[KK]; float ssum = 0.0f;
#pragma unroll
    for (int k = 0; k < KK; k++) { w[k] = expf(tvk[k] - m); ssum += w[k]; }
    const float inv = 1.0f / ssum;

    // cooperative gather: lane owns channels 2*lane, 2*lane+1
    float ax = 0.f, ay = 0.f;
#pragma unroll
    for (int k = 0; k < KK; k++) {
        const float wk = w[k] * inv;
        const float2 r = *(const float2*)&rsrc[(size_t)tik[k] * DD + 2*lane];
        ax += wk * r.x; ay += wk * r.y;
    }
    *(float2*)&dst[2*lane] = make_float2(ax, ay);
}

// ============================================================================
// Winner pass (last-wins scatter semantics: max pillar index per cell)
// ============================================================================
__global__ void k_winner_init() {
    int i = blockIdx.x * 256 + threadIdx.x;
    if (i < BB * HW) g_winner[i] = -1;
}

__global__ void k_winner_mark(const int* __restrict__ idx) {
    int g = blockIdx.x * 256 + threadIdx.x;
    if (g >= BPP) return;
    int b = g / PP;
    atomicMax(&g_winner[b * HW + idx[g]], g - b * PP);
}

// ============================================================================
// Dense gather-fill: each thread owns 4 consecutive grid cells (winner int4 in
// registers), loops over 32 channel-planes writing coalesced float4 stores.
// Planes t: [0,64) grid1/pillars, [64,128) grid1/pos_mem,
//           [128,192) grid2/pillars, [192,256) grid2/pos_point,
//           [256,320) grid3/scale.
// ============================================================================
__global__ void __launch_bounds__(256)
k_fill(const float* __restrict__ pillars, const float* __restrict__ scale,
       const float* __restrict__ pos_point, const float* __restrict__ pos_mem,
       float* __restrict__ out)
{
    const int b = blockIdx.z;
    const int hw = (blockIdx.x * 256 + threadIdx.x) * 4;
    if (hw >= HW) return;

    const int4 w = *(const int4*)&g_winner[b * HW + hw];
    const int wm = max(max(w.x, w.y), max(w.z, w.w));
    const bool any = (wm >= 0);
    const size_t G1 = (size_t)BB * 128 * HW;

    const int t0 = blockIdx.y * PLANES_PER_BLK;
#pragma unroll 4
    for (int t = t0; t < t0 + PLANES_PER_BLK; t++) {
        const float* A; int cc; size_t ob;
        if (t < 64)       { A = pillars;   cc = t;       ob = ((size_t)b*128 + t) * HW; }
        else if (t < 128) { A = pos_mem;   cc = t - 64;  ob = ((size_t)b*128 + t) * HW; }
        else if (t < 192) { A = pillars;   cc = t - 128; ob = G1 + ((size_t)b*128 + (t-128)) * HW; }
        else if (t < 256) { A = pos_point; cc = t - 192; ob = G1 + ((size_t)b*128 + (t-128)) * HW; }
        else              { A = scale;     cc = t - 256; ob = 2*G1 + ((size_t)b*64 + (t-256)) * HW; }

        float4 v = make_float4(0.f, 0.f, 0.f, 0.f);
        if (any) {
            const float* Ab = A + (size_t)b * PP * 64 + cc;
            if (w.x >= 0) v.x = Ab[(size_t)w.x * 64];
            if (w.y >= 0) v.y = Ab[(size_t)w.y * 64];
            if (w.z >= 0) v.z = Ab[(size_t)w.z * 64];
            if (w.w >= 0) v.w = Ab[(size_t)w.w * 64];
        }
        *(float4*)(out + ob + hw) = v;
    }
}

// ============================================================================
// kernel_launch — graph-capturable, allocation-free.
// Inputs: pillar_features, pillar_scale_features, point_features,
//         memory_weight, indices
// Output: sp, sp_point, sp_scale, pos_point, pos_mem (fp32, concatenated)
// ============================================================================
extern "C" void kernel_launch(void* const* d_in, const int* in_sizes, int n_in,
                              void* d_out, int out_size)
{
    const float* pillars = (const float*)d_in[0];
    const float* scale   = (const float*)d_in[1];
    const float* points  = (const float*)d_in[2];
    const float* W       = (const float*)d_in[3];
    const int*   idx     = (const int*)  d_in[4];
    float* out = (float*)d_out;

    const size_t sz12  = (size_t)BB * 128 * HW;
    const size_t sz3   = (size_t)BB * 64 * HW;
    const size_t grids = 2 * sz12 + sz3;
    float* out4 = out + grids;                   // point_positive [B*P, 64]
    float* out5 = out4 + (size_t)BPP * DD;       // memory_positive [B*P, 64]

    // winner resolution first (only depends on idx)
    k_winner_init<<<(BB * HW + 255) / 256, 256>>>();
    k_winner_mark<<<(BPP + 255) / 256, 256>>>(idx);

    // both attention matmuls + top-8 in one launch (1536 blocks)
    k_topk_all<<<dim3((PP + 127) / 128, NSPLIT_PTS + NSPLIT_MEM, BB), 128>>>(
        pillars, points, W);

    // warp-per-task merge: 16000 warps
    k_merge_warp<<<(2 * BPP + 7) / 8, 256>>>(points, W, out4, out5);

    // dense gather-fill of all three grids (no memset needed)
    k_fill<<<dim3((HW / 4 + 255) / 256, PLANES / PLANES_PER_BLK, BB), 256>>>(
        pillars, scale, out4, out5, out);
}